// round 17
// baseline (speedup 1.0000x reference)
#include <cuda_runtime.h>
#include <cuda_bf16.h>
#include <cstdint>
#include <cstddef>

// Problem constants
#define B_   4
#define C_   384
#define S_   4096

typedef __nv_bfloat16 bf16;

// ---------------------------------------------------------------------------
// Scratch (device globals; no allocation allowed in kernel_launch)
// ---------------------------------------------------------------------------
__device__ float g_rs [B_ * S_];                          // softmax row sums
__device__ bf16  g_wg [3 * C_ * C_];                      // bf16(w_qkv * gamma)
__device__ bf16  g_wp [C_ * C_];                          // bf16(w_proj)
__device__ bf16  g_xnt[(size_t)B_ * S_ * C_];             // [b][s][c] normed x
__device__ bf16  g_qkt[(size_t)B_ * S_ * 2 * C_];         // [b][s][q|k]
__device__ bf16  g_v  [(size_t)B_ * C_ * S_];             // [b][c][s]
__device__ bf16  g_P  [(size_t)B_ * S_ * S_];             // [b][i][j] exp-scores
__device__ bf16  g_Ot [(size_t)B_ * S_ * C_];             // [b][s][c]

// ---------------------------------------------------------------------------
// PTX helpers (baseline ISA only)
// ---------------------------------------------------------------------------
#define CP_ASYNC16(dst, src) \
    asm volatile("cp.async.cg.shared.global [%0], [%1], 16;" :: "r"(dst), "l"(src))
#define CP_COMMIT() asm volatile("cp.async.commit_group;" ::: "memory")
#define CP_WAIT(n)  asm volatile("cp.async.wait_group %0;" :: "n"(n) : "memory")

__device__ __forceinline__ void ldsm4(uint32_t& r0, uint32_t& r1, uint32_t& r2,
                                      uint32_t& r3, uint32_t addr) {
    asm volatile("ldmatrix.sync.aligned.m8n8.x4.shared.b16 {%0,%1,%2,%3}, [%4];"
                 : "=r"(r0), "=r"(r1), "=r"(r2), "=r"(r3) : "r"(addr));
}

__device__ __forceinline__ void mma16(float* c, const uint32_t* a, const uint32_t* b) {
    asm volatile(
        "mma.sync.aligned.m16n8k16.row.col.f32.bf16.bf16.f32 "
        "{%0,%1,%2,%3}, {%4,%5,%6,%7}, {%8,%9}, {%0,%1,%2,%3};"
        : "+f"(c[0]), "+f"(c[1]), "+f"(c[2]), "+f"(c[3])
        : "r"(a[0]), "r"(a[1]), "r"(a[2]), "r"(a[3]), "r"(b[0]), "r"(b[1]));
}

// ---------------------------------------------------------------------------
// Prep kernels
// ---------------------------------------------------------------------------
// merged weight convert + rs zeroing
__global__ void wcvt_kernel(bf16* __restrict__ wg, bf16* __restrict__ wp,
                            const float* __restrict__ wq, const float* __restrict__ g,
                            const float* __restrict__ wpr, float* __restrict__ rs) {
    int i = blockIdx.x * 256 + threadIdx.x;
    if (i < 3 * C_ * C_) wg[i] = __float2bfloat16_rn(wq[i] * g[i % C_]);
    if (i < C_ * C_)     wp[i] = __float2bfloat16_rn(wpr[i]);
    if (i < B_ * S_)     rs[i] = 0.f;
}

// fused rms-norm + transpose: one pass over x.
__global__ void norm_kernel(bf16* __restrict__ xnt, const float* __restrict__ x) {
    extern __shared__ float t[];                 // [384][33]
    __shared__ float red[8][32];
    __shared__ float sscl[32];
    const int tx = threadIdx.x, ty = threadIdx.y;
    const int tid = ty * 32 + tx;
    const int s0 = blockIdx.x * 32;
    const int b  = blockIdx.y;
    const float* xb = x + (size_t)b * C_ * S_ + s0 + tx;

    float acc = 0.f;
#pragma unroll
    for (int i = 0; i < 48; ++i) {
        const int c = ty + i * 8;
        float v = xb[(size_t)c * S_];
        t[c * 33 + tx] = v;
        acc += v * v;
    }
    red[ty][tx] = acc;
    __syncthreads();
    if (ty == 0) {
        float u = red[0][tx];
#pragma unroll
        for (int j = 1; j < 8; ++j) u += red[j][tx];
        float l2 = sqrtf(u);
        sscl[tx] = 19.595917942265423f / fmaxf(l2, 1e-12f);  // sqrt(384)/max(l2,eps)
    }
    __syncthreads();

    bf16* o = xnt + (size_t)b * S_ * C_ + (size_t)s0 * C_;
#pragma unroll
    for (int i = 0; i < 48; ++i) {
        const int idx = i * 256 + tid;           // over 32*384 outputs [s][c]
        const int s = idx / C_;
        const int c = idx - s * C_;
        o[idx] = __float2bfloat16_rn(t[c * 33 + s] * sscl[s]);
    }
}

// ---------------------------------------------------------------------------
// Shared GEMM tile machinery (R8-proven): 128x128 block tile, 8 warps
// (4M x 2N, warp tile 32x64), Kc=32, 4-stage cp.async pipeline.
// ---------------------------------------------------------------------------
#define SRB    80                    // bytes per smem row (64 data + 16 pad)
#define ATILEB (128 * SRB)           // 10240 B per operand tile
#define STGB   (2 * ATILEB)          // 20480 B per stage
#define NSTG   4

#define GEMM_MAINLOOP(A, Bp, lda, ldb, K)                                        \
    const uint32_t smB = (uint32_t)__cvta_generic_to_shared(smem);               \
    const int lr = tid >> 2;                                                     \
    const int lq = (tid & 3) * 8;                                                \
    const uint32_t lqB = (uint32_t)(tid & 3) * 16;                               \
    const int g = lane >> 3, r = lane & 7;                                       \
    const uint32_t aOff = (uint32_t)((warpM * 32 + (g & 1) * 8 + r) * SRB + (g >> 1) * 16); \
    const uint32_t bOff = (uint32_t)(ATILEB + (warpN * 64 + (g & 1) * 8 + r) * SRB + (g >> 1) * 16); \
    float acc[2][8][4];                                                          \
    _Pragma("unroll")                                                            \
    for (int mf = 0; mf < 2; ++mf)                                               \
        _Pragma("unroll")                                                        \
        for (int nf = 0; nf < 8; ++nf)                                           \
            _Pragma("unroll")                                                    \
            for (int i = 0; i < 4; ++i) acc[mf][nf][i] = 0.f;                    \
    const int nK = (K) >> 5;                                                     \
    auto LOAD = [&](int s) {                                                     \
        const int p = s & (NSTG - 1);                                            \
        const bf16* As = (A)  + (size_t)lr * (lda) + s * 32 + lq;                \
        const bf16* Bs = (Bp) + (size_t)lr * (ldb) + s * 32 + lq;                \
        uint32_t dA = smB + (uint32_t)(p * STGB + lr * SRB) + lqB;               \
        uint32_t dB = dA + (uint32_t)ATILEB;                                     \
        CP_ASYNC16(dA,            As);                                           \
        CP_ASYNC16(dA + 64 * SRB, As + (size_t)64 * (lda));                      \
        CP_ASYNC16(dB,            Bs);                                           \
        CP_ASYNC16(dB + 64 * SRB, Bs + (size_t)64 * (ldb));                      \
    };                                                                           \
    LOAD(0); CP_COMMIT();                                                        \
    LOAD(1); CP_COMMIT();                                                        \
    LOAD(2); CP_COMMIT();                                                        \
    for (int s = 0; s < nK; ++s) {                                               \
        CP_WAIT(2);                                                              \
        __syncthreads();                                                         \
        if (s + 3 < nK) LOAD(s + 3);                                             \
        CP_COMMIT();                                                             \
        const uint32_t pb = smB + (uint32_t)((s & (NSTG - 1)) * STGB);           \
        _Pragma("unroll")                                                        \
        for (int kk = 0; kk < 2; ++kk) {                                         \
            uint32_t afr[2][4], bfr[8][2];                                       \
            _Pragma("unroll")                                                    \
            for (int mf = 0; mf < 2; ++mf)                                       \
                ldsm4(afr[mf][0], afr[mf][1], afr[mf][2], afr[mf][3],            \
                      pb + aOff + (uint32_t)(mf * 16 * SRB + kk * 32));          \
            _Pragma("unroll")                                                    \
            for (int pr = 0; pr < 4; ++pr)                                       \
                ldsm4(bfr[2 * pr][0], bfr[2 * pr + 1][0],                        \
                      bfr[2 * pr][1], bfr[2 * pr + 1][1],                        \
                      pb + bOff + (uint32_t)(pr * 16 * SRB + kk * 32));          \
            _Pragma("unroll")                                                    \
            for (int mf = 0; mf < 2; ++mf)                                       \
                _Pragma("unroll")                                                \
                for (int nf = 0; nf < 8; ++nf)                                   \
                    mma16(acc[mf][nf], afr[mf], bfr[nf]);                        \
        }                                                                        \
    }

// ---------------------------------------------------------------------------
// Combined qkv + v GEMM (independent tiles packed into one launch).
// ---------------------------------------------------------------------------
__global__ __launch_bounds__(256)
void qkv_v_gemm(const bf16* __restrict__ xnt, const bf16* __restrict__ wg,
                bf16* __restrict__ qkt, bf16* __restrict__ vout,
                const float* __restrict__ bq)
{
    extern __shared__ __align__(16) char smem[];
    const int tid  = threadIdx.x;
    const int lane = tid & 31, wid = tid >> 5;
    const int warpM = wid & 3, warpN = wid >> 2;
    const int bz = blockIdx.z;
    const int t = blockIdx.x;
    const bool isQ = t < 192;

    const bf16 *A, *Bp;
    bf16* Cp;
    int ldc, m0, n0;
    const float* bias;
    if (isQ) {
        int bx = t % 6, by = t / 6;
        m0 = by * 128; n0 = bx * 128;
        A  = xnt + (size_t)bz * S_ * C_ + (size_t)m0 * C_;
        Bp = wg + (size_t)n0 * C_;
        Cp = qkt + (size_t)bz * S_ * 2 * C_;
        ldc = 2 * C_;
        bias = bq;
    } else {
        int t2 = t - 192;
        int bx = t2 % 32, by = t2 / 32;
        m0 = by * 128; n0 = bx * 128;
        A  = wg + (size_t)2 * C_ * C_ + (size_t)m0 * C_;
        Bp = xnt + (size_t)bz * S_ * C_ + (size_t)n0 * C_;
        Cp = vout + (size_t)bz * C_ * S_;
        ldc = S_;
        bias = bq + 2 * C_;
    }

    GEMM_MAINLOOP(A, Bp, C_, C_, C_)

    // epilogue
    const int rBase = m0 + warpM * 32 + (lane >> 2);
    const int cBase = n0 + warpN * 64 + (lane & 3) * 2;
#pragma unroll
    for (int mf = 0; mf < 2; ++mf) {
#pragma unroll
        for (int h = 0; h < 2; ++h) {
            const int row = rBase + mf * 16 + h * 8;
            float bm = isQ ? 0.f : bias[row];
#pragma unroll
            for (int nf = 0; nf < 8; ++nf) {
                const int col = cBase + nf * 8;
                float u0 = acc[mf][nf][2 * h];
                float u1 = acc[mf][nf][2 * h + 1];
                float2 o;
                if (isQ) {
                    float2 bn = *(const float2*)(bias + col);
                    o.x = u0 + bn.x; o.y = u1 + bn.y;
                } else {
                    o.x = u0 + bm; o.y = u1 + bm;
                }
                bf16* Crow = Cp + (size_t)row * ldc;
                __nv_bfloat162 hv = __floats2bfloat162_rn(o.x, o.y);
                *(__nv_bfloat162*)(Crow + col) = hv;
            }
        }
    }
}

// ---------------------------------------------------------------------------
// Scores GEMM: 256x128 block tile, 512 threads (8M x 2N warps of 32x64).
// 1 CTA/SM (120KB smem) but 16 warps/SM; halves per-CTA prologue/epilogue
// overhead vs the 128-tile version (2048 CTAs instead of 4096).
// P[i][j] = exp2((q_i.k_j) * log2e/sqrt(C)) -> bf16; rs[i] += row sums.
// ---------------------------------------------------------------------------
#define S_ROWS 384                    // 256 A rows + 128 B rows per stage
#define S_STGB (S_ROWS * SRB)         // 30720 B per stage

__global__ __launch_bounds__(512)
void scores_gemm(const bf16* __restrict__ qkt, bf16* __restrict__ P,
                 float* __restrict__ rs)
{
    extern __shared__ __align__(16) char smem[];   // NSTG * S_STGB

    const int tid  = threadIdx.x;                  // 0..511
    const int lane = tid & 31, wid = tid >> 5;     // 16 warps
    const int warpM = wid & 7, warpN = wid >> 3;   // 8M x 2N
    const int bz = blockIdx.z;
    const int m0 = blockIdx.y * 256, n0 = blockIdx.x * 128;
    const int ld = 2 * C_;                         // 768

    const bf16* A  = qkt + (size_t)bz * S_ * ld + (size_t)m0 * ld;        // q rows
    const bf16* Bp = qkt + C_ + (size_t)bz * S_ * ld + (size_t)n0 * ld;   // k rows
    const uint32_t smB = (uint32_t)__cvta_generic_to_shared(smem);

    // loader: 512 threads x 3 chunks cover 384 rows x 64B per stage
    const int lr = tid >> 2;                         // 0..127
    const int lq = (tid & 3) * 8;
    const uint32_t lqB = (uint32_t)(tid & 3) * 16;

    const int g = lane >> 3, r = lane & 7;
    const uint32_t aOff = (uint32_t)((warpM * 32 + (g & 1) * 8 + r) * SRB + (g >> 1) * 16);
    const uint32_t bOff = (uint32_t)(256 * SRB + (warpN * 64 + (g & 1) * 8 + r) * SRB + (g >> 1) * 16);

    float acc[2][8][4];
#pragma unroll
    for (int mf = 0; mf < 2; ++mf)
#pragma unroll
        for (int nf = 0; nf < 8; ++nf)
#pragma unroll
            for (int i = 0; i < 4; ++i) acc[mf][nf][i] = 0.f;

    const int nK = C_ >> 5;   // 12 stages

    auto LOAD = [&](int s) {
        const int p = s & (NSTG - 1);
        const bf16* As = A  + (size_t)lr * ld + s * 32 + lq;
        const bf16* Bs = Bp + (size_t)lr * ld + s * 32 + lq;
        uint32_t dA = smB + (uint32_t)(p * S_STGB + lr * SRB) + lqB;
        CP_ASYNC16(dA,             As);
        CP_ASYNC16(dA + 128 * SRB, As + (size_t)128 * ld);
        CP_ASYNC16(dA + 256 * SRB, Bs);
    };

    LOAD(0); CP_COMMIT();
    LOAD(1); CP_COMMIT();
    LOAD(2); CP_COMMIT();

    for (int s = 0; s < nK; ++s) {
        CP_WAIT(2);
        __syncthreads();
        if (s + 3 < nK) LOAD(s + 3);
        CP_COMMIT();

        const uint32_t pb = smB + (uint32_t)((s & (NSTG - 1)) * S_STGB);
#pragma unroll
        for (int kk = 0; kk < 2; ++kk) {
            uint32_t afr[2][4], bfr[8][2];
#pragma unroll
            for (int mf = 0; mf < 2; ++mf)
                ldsm4(afr[mf][0], afr[mf][1], afr[mf][2], afr[mf][3],
                      pb + aOff + (uint32_t)(mf * 16 * SRB + kk * 32));
#pragma unroll
            for (int pr = 0; pr < 4; ++pr)
                ldsm4(bfr[2 * pr][0], bfr[2 * pr + 1][0],
                      bfr[2 * pr][1], bfr[2 * pr + 1][1],
                      pb + bOff + (uint32_t)(pr * 16 * SRB + kk * 32));
#pragma unroll
            for (int mf = 0; mf < 2; ++mf)
#pragma unroll
                for (int nf = 0; nf < 8; ++nf)
                    mma16(acc[mf][nf], afr[mf], bfr[nf]);
        }
    }

    // ---- epilogue: exp2 + bf16 store + row-sum atomics ----
    const float sc2 = 0.07362222279181894f;   // log2(e)/sqrt(384)
    const int rBase = m0 + warpM * 32 + (lane >> 2);
    const int cBase = n0 + warpN * 64 + (lane & 3) * 2;
    float* rsb = rs + (size_t)bz * S_;
    bf16* Pb = P + (size_t)bz * S_ * S_;
#pragma unroll
    for (int mf = 0; mf < 2; ++mf) {
#pragma unroll
        for (int h = 0; h < 2; ++h) {
            const int row = rBase + mf * 16 + h * 8;
            bf16* Crow = Pb + (size_t)row * S_;
            float rsum = 0.f;
#pragma unroll
            for (int nf = 0; nf < 8; ++nf) {
                const int col = cBase + nf * 8;
                float o0 = exp2f(acc[mf][nf][2 * h] * sc2);
                float o1 = exp2f(acc[mf][nf][2 * h + 1] * sc2);
                rsum += o0 + o1;
                __nv_bfloat162 hv = __floats2bfloat162_rn(o0, o1);
                *(__nv_bfloat162*)(Crow + col) = hv;
            }
            rsum += __shfl_xor_sync(0xffffffffu, rsum, 1);
            rsum += __shfl_xor_sync(0xffffffffu, rsum, 2);
            if ((lane & 3) == 0) atomicAdd(rsb + row, rsum);
        }
    }
}

// ---------------------------------------------------------------------------
// Templated GEMM for AV / proj.
//   EPI 3: * 1/e3[row] -> bf16  (AV normalize by softmax row sum)
//   EPI 4: +e2[m] + e3[m*ldc+n] -> fp32 (proj bias + residual)
// ---------------------------------------------------------------------------
template <int EPI>
__global__ __launch_bounds__(256)
void mma_gemm(const bf16* __restrict__ Ag, const bf16* __restrict__ Bg,
              void* __restrict__ Cgv, int K, int lda, int ldb, int ldc,
              size_t sA, size_t sB, size_t sC,
              const float* __restrict__ e2, const float* __restrict__ e3,
              size_t e3s)
{
    extern __shared__ __align__(16) char smem[];
    const int tid  = threadIdx.x;
    const int lane = tid & 31, wid = tid >> 5;
    const int warpM = wid & 3, warpN = wid >> 2;
    const int bz = blockIdx.z;
    const int m0 = blockIdx.y * 128, n0 = blockIdx.x * 128;

    const bf16* A  = Ag + (size_t)bz * sA + (size_t)m0 * lda;
    const bf16* Bp = Bg + (size_t)bz * sB + (size_t)n0 * ldb;

    GEMM_MAINLOOP(A, Bp, lda, ldb, K)

    // ---- epilogue ----
    const int rBase = m0 + warpM * 32 + (lane >> 2);
    const int cBase = n0 + warpN * 64 + (lane & 3) * 2;
#pragma unroll
    for (int mf = 0; mf < 2; ++mf) {
#pragma unroll
        for (int h = 0; h < 2; ++h) {
            const int row = rBase + mf * 16 + h * 8;
            float bm = 0.f;
            if (EPI == 4) bm = e2[row];
            float inv = 1.f;
            if (EPI == 3) inv = 1.f / e3[(size_t)bz * e3s + row];
#pragma unroll
            for (int nf = 0; nf < 8; ++nf) {
                const int col = cBase + nf * 8;
                float u0 = acc[mf][nf][2 * h];
                float u1 = acc[mf][nf][2 * h + 1];
                float2 o;
                if (EPI == 3) {
                    o.x = u0 * inv; o.y = u1 * inv;
                } else {
                    const float* e3row = e3 + (size_t)bz * e3s + (size_t)row * ldc;
                    float2 rx = *(const float2*)(e3row + col);
                    o.x = u0 + bm + rx.x; o.y = u1 + bm + rx.y;
                }
                if (EPI == 4) {
                    float* Crow = (float*)Cgv + (size_t)bz * sC + (size_t)row * ldc;
                    *(float2*)(Crow + col) = o;
                } else {
                    bf16* Crow = (bf16*)Cgv + (size_t)bz * sC + (size_t)row * ldc;
                    __nv_bfloat162 hv = __floats2bfloat162_rn(o.x, o.y);
                    *(__nv_bfloat162*)(Crow + col) = hv;
                }
            }
        }
    }
}

// ---------------------------------------------------------------------------
// Launch
// ---------------------------------------------------------------------------
extern "C" void kernel_launch(void* const* d_in, const int* in_sizes, int n_in,
                              void* d_out, int out_size) {
    const float* x      = (const float*)d_in[0];   // [4,384,64,64]
    const float* gamma  = (const float*)d_in[1];   // [384]
    const float* w_qkv  = (const float*)d_in[2];   // [1152,384]
    const float* b_qkv  = (const float*)d_in[3];   // [1152]
    const float* w_proj = (const float*)d_in[4];   // [384,384]
    const float* b_proj = (const float*)d_in[5];   // [384]
    float* out = (float*)d_out;                    // [4,384,64,64]

    float *rs;
    bf16 *wg, *wp, *xnt, *qkt, *v, *P, *Ot;
    cudaGetSymbolAddress((void**)&rs,  g_rs);
    cudaGetSymbolAddress((void**)&wg,  g_wg);
    cudaGetSymbolAddress((void**)&wp,  g_wp);
    cudaGetSymbolAddress((void**)&xnt, g_xnt);
    cudaGetSymbolAddress((void**)&qkt, g_qkt);
    cudaGetSymbolAddress((void**)&v,   g_v);
    cudaGetSymbolAddress((void**)&P,   g_P);
    cudaGetSymbolAddress((void**)&Ot,  g_Ot);

    const int SMEM_DYN = NSTG * STGB;        // 81920 bytes
    const int SMEM_SC  = NSTG * S_STGB;      // 122880 bytes
    cudaFuncSetAttribute((const void*)qkv_v_gemm, cudaFuncAttributeMaxDynamicSharedMemorySize, SMEM_DYN);
    cudaFuncSetAttribute((const void*)scores_gemm, cudaFuncAttributeMaxDynamicSharedMemorySize, SMEM_SC);
    cudaFuncSetAttribute((const void*)mma_gemm<3>, cudaFuncAttributeMaxDynamicSharedMemorySize, SMEM_DYN);
    cudaFuncSetAttribute((const void*)mma_gemm<4>, cudaFuncAttributeMaxDynamicSharedMemorySize, SMEM_DYN);
    const int NORM_SMEM = C_ * 33 * 4;  // 50688 bytes
    cudaFuncSetAttribute((const void*)norm_kernel, cudaFuncAttributeMaxDynamicSharedMemorySize, NORM_SMEM);

    // 1) weight converts + rs zeroing (one launch)
    wcvt_kernel<<<(3 * C_ * C_ + 255) / 256, 256>>>(wg, wp, w_qkv, gamma, w_proj, rs);
    // 2) fused rms-norm + transpose: xnt[b][s][c] (single pass over x)
    norm_kernel<<<dim3(S_ / 32, B_), dim3(32, 8), NORM_SMEM>>>(xnt, x);
    // 3) combined qkv + v GEMM (288 tiles/batch packed in one launch)
    qkv_v_gemm<<<dim3(288, 1, B_), 256, SMEM_DYN>>>(xnt, wg, qkt, v, b_qkv);
    // 4) P = exp(q.k/sqrt(C)) + row sums, 256x128 tiles  (2048 CTAs)
    scores_gemm<<<dim3(32, 16, B_), 512, SMEM_SC>>>(qkt, P, rs);
    // 5) Ot[b][i][c] = (P @ v^T) / rs[b][i]                M=4096 N=384 K=4096
    mma_gemm<3><<<dim3(3, 32, B_), 256, SMEM_DYN>>>(
        P, v, Ot, S_, S_, S_, C_,
        (size_t)S_ * S_, (size_t)C_ * S_, (size_t)S_ * C_,
        nullptr, rs, S_);
    // 6) out[b][o][s] = Wp @ Ot^T + b_proj[o] + x          M=384 N=4096 K=384
    mma_gemm<4><<<dim3(32, 3, B_), 256, SMEM_DYN>>>(
        wp, Ot, out, C_, C_, C_, S_,
        0, (size_t)S_ * C_, (size_t)C_ * S_, b_proj, x, (size_t)C_ * S_);
}